// round 5
// baseline (speedup 1.0000x reference)
#include <cuda_runtime.h>
#include <math.h>

typedef unsigned int u32;
typedef unsigned long long u64;

#define NLEV 16
#define HSIZE (1u << 19)
#define HMASK (HSIZE - 1u)
#define NPTS (4096 * 128)

struct Consts { float res[NLEV]; };

// all MLP weights live in the constant bank: warp-uniform reads go through
// the constant port (LDC), leaving L1tex to the hash-table gathers only.
__constant__ float c_win[32 * 64];    //  8 KB
__constant__ float c_wout[64 * 16];   //  4 KB
__constant__ float c_w1[15 * 64];     //  3.75 KB
__constant__ float c_w2[64 * 64];     // 16 KB
__constant__ float c_w3[64 * 3];      //  0.75 KB

// ---------- packed f32x2 helpers ----------
__device__ __forceinline__ u64 pk2(float a, float b) {
    u64 r; asm("mov.b64 %0,{%1,%2};" : "=l"(r) : "f"(a), "f"(b)); return r;
}
__device__ __forceinline__ void up2(u64 v, float& a, float& b) {
    asm("mov.b64 {%0,%1},%2;" : "=f"(a), "=f"(b) : "l"(v));
}
__device__ __forceinline__ u64 f2fma(u64 a, u64 b, u64 c) {
    u64 d; asm("fma.rn.f32x2 %0,%1,%2,%3;" : "=l"(d) : "l"(a), "l"(b), "l"(c)); return d;
}

// fused: hash encode -> density MLP -> volrend scan -> rgb MLP.
// 1 point per thread; one block (128 threads) == one ray (128 samples).
__global__ void __launch_bounds__(128, 4) fused_point_kernel(
    const float* __restrict__ xyz, const float* __restrict__ delta,
    const float* __restrict__ table, float4* __restrict__ out, Consts cc,
    float offset)
{
    __shared__ float wsum[4];
    const int t = threadIdx.x;
    const int p = blockIdx.x * 128 + t;
    const float px = __ldg(xyz + 3 * p);
    const float py = __ldg(xyz + 3 * p + 1);
    const float pz = __ldg(xyz + 3 * p + 2);

    // ---- hash-grid encode fused with layer 1 (enc @ w_in) ----
    u64 hA[32];
    #pragma unroll
    for (int j = 0; j < 32; j++) hA[j] = 0ULL;

    #pragma unroll 2
    for (int l = 0; l < NLEV; l++) {
        const float r = cc.res[l];
        const float X = px * r, Y = py * r, Z = pz * r;
        const float fx = floorf(X), fy = floorf(Y), fz = floorf(Z);
        const float ax = X - fx, ay = Y - fy, az = Z - fz;
        const u32 ix = (u32)fx, iy = (u32)fy, iz = (u32)fz;
        const u32 hx0 = ix, hx1 = ix + 1u;
        const u32 hy0 = iy * 2654435761u, hy1 = hy0 + 2654435761u;
        const u32 hz0 = iz * 805459861u,  hz1 = hz0 + 805459861u;
        const float2* tab = (const float2*)table + (size_t)l * HSIZE;

        // batch all 8 gathers first (8-deep MLP within the warp)
        float2 tv[8];
        #pragma unroll
        for (int c = 0; c < 8; c++) {
            const u32 hx = (c & 4) ? hx1 : hx0;
            const u32 hy = (c & 2) ? hy1 : hy0;
            const u32 hz = (c & 1) ? hz1 : hz0;
            tv[c] = __ldg(tab + ((hx ^ hy ^ hz) & HMASK));
        }

        const float bx = 1.f - ax, by = 1.f - ay, bz = 1.f - az;
        float a0 = 0.f, a1 = 0.f;
        #pragma unroll
        for (int c = 0; c < 8; c++) {
            const float w = ((c & 4) ? ax : bx) * ((c & 2) ? ay : by) * ((c & 1) ? az : bz);
            a0 = fmaf(w, tv[c].x, a0);
            a1 = fmaf(w, tv[c].y, a1);
        }

        const u64 e0 = pk2(a0, a0), e1 = pk2(a1, a1);
        const u64* r0 = (const u64*)(c_win + (2 * l) * 64);
        const u64* r1 = r0 + 32;
        #pragma unroll
        for (int j = 0; j < 32; j += 2) {
            const ulonglong2 wv0 = *(const ulonglong2*)(r0 + j);
            const ulonglong2 wv1 = *(const ulonglong2*)(r1 + j);
            hA[j]     = f2fma(e1, wv1.x, f2fma(e0, wv0.x, hA[j]));
            hA[j + 1] = f2fma(e1, wv1.y, f2fma(e0, wv0.y, hA[j + 1]));
        }
    }

    // ---- layer 2: raw = relu(h) @ w_out  (16 outputs) ----
    u64 raw2[8];
    #pragma unroll
    for (int j = 0; j < 8; j++) raw2[j] = 0ULL;
    #pragma unroll
    for (int ic = 0; ic < 32; ic++) {
        float v0, v1; up2(hA[ic], v0, v1);
        v0 = fmaxf(v0, 0.f); v1 = fmaxf(v1, 0.f);
        const u64 e0 = pk2(v0, v0), e1 = pk2(v1, v1);
        const u64* r0 = (const u64*)(c_wout + (2 * ic) * 16);
        const u64* r1 = r0 + 8;
        #pragma unroll
        for (int j = 0; j < 8; j += 2) {
            const ulonglong2 wv0 = *(const ulonglong2*)(r0 + j);
            const ulonglong2 wv1 = *(const ulonglong2*)(r1 + j);
            raw2[j]     = f2fma(e1, wv1.x, f2fma(e0, wv0.x, raw2[j]));
            raw2[j + 1] = f2fma(e1, wv1.y, f2fma(e0, wv0.y, raw2[j + 1]));
        }
    }
    float raw[16];
    #pragma unroll
    for (int j = 0; j < 8; j++) up2(raw2[j], raw[2 * j], raw[2 * j + 1]);

    // ---- volume-rendering weights: block-wide exclusive scan (1 ray/block) ----
    const float dd = expf(raw[0] + offset + logf(__ldg(delta + p)));
    float s = dd;
    const int lane = t & 31, wid = t >> 5;
    #pragma unroll
    for (int o = 1; o < 32; o <<= 1) {
        const float v = __shfl_up_sync(0xffffffffu, s, o);
        if (lane >= o) s += v;
    }
    if (lane == 31) wsum[wid] = s;
    __syncthreads();
    float pref = 0.f;
    #pragma unroll
    for (int w = 0; w < 3; w++) if (wid > w) pref += wsum[w];
    const float excl = pref + s - dd;
    const float wgt = (1.f - expf(-dd)) * expf(-excl);

    // ---- rgb layer 1: h1 = relu(feats @ rgb_w1), feats = raw[1..15] ----
    #pragma unroll
    for (int j = 0; j < 32; j++) hA[j] = 0ULL;
    #pragma unroll
    for (int i = 0; i < 15; i++) {
        const u64 e = pk2(raw[i + 1], raw[i + 1]);
        const u64* row = (const u64*)(c_w1 + i * 64);
        #pragma unroll
        for (int j = 0; j < 32; j += 2) {
            const ulonglong2 wv = *(const ulonglong2*)(row + j);
            hA[j]     = f2fma(e, wv.x, hA[j]);
            hA[j + 1] = f2fma(e, wv.y, hA[j + 1]);
        }
    }
    // relu in place
    #pragma unroll
    for (int j = 0; j < 32; j++) {
        float v0, v1; up2(hA[j], v0, v1);
        hA[j] = pk2(fmaxf(v0, 0.f), fmaxf(v1, 0.f));
    }

    // ---- rgb layers 2+3, blocked over 4 groups of 16 outputs ----
    float cr = 0.f, cg = 0.f, cb = 0.f;
    #pragma unroll
    for (int ob = 0; ob < 4; ob++) {
        u64 acc[8];
        #pragma unroll
        for (int j = 0; j < 8; j++) acc[j] = 0ULL;
        #pragma unroll
        for (int ic = 0; ic < 32; ic++) {
            float v0, v1; up2(hA[ic], v0, v1);
            const u64 e0 = pk2(v0, v0), e1 = pk2(v1, v1);
            const u64* r0 = (const u64*)(c_w2 + (2 * ic) * 64 + ob * 16);
            const u64* r1 = r0 + 32;
            #pragma unroll
            for (int j = 0; j < 8; j += 2) {
                const ulonglong2 wv0 = *(const ulonglong2*)(r0 + j);
                const ulonglong2 wv1 = *(const ulonglong2*)(r1 + j);
                acc[j]     = f2fma(e1, wv1.x, f2fma(e0, wv0.x, acc[j]));
                acc[j + 1] = f2fma(e1, wv1.y, f2fma(e0, wv0.y, acc[j + 1]));
            }
        }
        #pragma unroll
        for (int j = 0; j < 8; j++) {
            float v0, v1; up2(acc[j], v0, v1);
            v0 = fmaxf(v0, 0.f); v1 = fmaxf(v1, 0.f);
            const float* q = c_w3 + (ob * 16 + 2 * j) * 3;
            cr = fmaf(v0, q[0], fmaf(v1, q[3], cr));
            cg = fmaf(v0, q[1], fmaf(v1, q[4], cg));
            cb = fmaf(v0, q[2], fmaf(v1, q[5], cb));
        }
    }

    out[p] = make_float4(wgt, 1.f / (1.f + expf(-cr)),
                         1.f / (1.f + expf(-cg)), 1.f / (1.f + expf(-cb)));
}

// pads FIRST: harness has 2 internal launches before ours, so global launch
// idx 5 (ncu -s 5 -c 1, kernel launches only) = our 4th launch = fused kernel.
__global__ void pad_kernel() {}

extern "C" void kernel_launch(void* const* d_in, const int* in_sizes, int n_in,
                              void* d_out, int out_size)
{
    const float* xyz   = (const float*)d_in[0];
    const float* delta = (const float*)d_in[1];
    const float* table = (const float*)d_in[2];
    const float* w_in  = (const float*)d_in[3];
    const float* w_out = (const float*)d_in[4];
    const float* rw1   = (const float*)d_in[5];
    const float* rw2   = (const float*)d_in[6];
    const float* rw3   = (const float*)d_in[7];
    float4* out = (float4*)d_out;

    Consts cc;
    const double scale = exp((log(4096.0) - log(16.0)) / 15.0);
    for (int l = 0; l < NLEV; l++)
        cc.res[l] = (float)floor(16.0 * pow(scale, (double)l));
    const float offset = (float)(log(log(1.0 / 0.99)) - log(6.0 - 2.0) - 0.5);

    // stage weights into the constant bank (D2D memcpy nodes; capture-legal)
    cudaMemcpyToSymbolAsync(c_win,  w_in,  32 * 64 * sizeof(float), 0, cudaMemcpyDeviceToDevice);
    cudaMemcpyToSymbolAsync(c_wout, w_out, 64 * 16 * sizeof(float), 0, cudaMemcpyDeviceToDevice);
    cudaMemcpyToSymbolAsync(c_w1,   rw1,   15 * 64 * sizeof(float), 0, cudaMemcpyDeviceToDevice);
    cudaMemcpyToSymbolAsync(c_w2,   rw2,   64 * 64 * sizeof(float), 0, cudaMemcpyDeviceToDevice);
    cudaMemcpyToSymbolAsync(c_w3,   rw3,   64 * 3  * sizeof(float), 0, cudaMemcpyDeviceToDevice);

    pad_kernel<<<1, 1>>>();
    pad_kernel<<<1, 1>>>();
    pad_kernel<<<1, 1>>>();
    fused_point_kernel<<<NPTS / 128, 128>>>(xyz, delta, table, out, cc, offset);
}

// round 6
// speedup vs baseline: 1.5211x; 1.5211x over previous
#include <cuda_runtime.h>
#include <math.h>

typedef unsigned int u32;
typedef unsigned long long u64;

#define NLEV 16
#define HSIZE (1u << 19)
#define HMASK (HSIZE - 1u)
#define NPTS (4096 * 128)

struct Consts { float res[NLEV]; };

// ---------- packed f32x2 helpers ----------
__device__ __forceinline__ u64 pk2(float a, float b) {
    u64 r; asm("mov.b64 %0,{%1,%2};" : "=l"(r) : "f"(a), "f"(b)); return r;
}
__device__ __forceinline__ void up2(u64 v, float& a, float& b) {
    asm("mov.b64 {%0,%1},%2;" : "=f"(a), "=f"(b) : "l"(v));
}
__device__ __forceinline__ u64 f2fma(u64 a, u64 b, u64 c) {
    u64 d; asm("fma.rn.f32x2 %0,%1,%2,%3;" : "=l"(d) : "l"(a), "l"(b), "l"(c)); return d;
}

struct __align__(16) SW {
    float win[32 * 64];   // 2048
    float wout[64 * 16];  // 1024
    float w1[15 * 64];    // 960
    float w2[64 * 64];    // 4096
    float w3[64 * 3];     // 192
};

// hash + issue the 8 gathers for one level into tv; returns fracs
__device__ __forceinline__ void level_fetch(
    float px, float py, float pz, float r,
    const float2* __restrict__ tab,
    float2 tv[8], float& ax, float& ay, float& az)
{
    const float X = px * r, Y = py * r, Z = pz * r;
    const float fx = floorf(X), fy = floorf(Y), fz = floorf(Z);
    ax = X - fx; ay = Y - fy; az = Z - fz;
    const u32 ix = (u32)fx, iy = (u32)fy, iz = (u32)fz;
    const u32 hx0 = ix, hx1 = ix + 1u;
    const u32 hy0 = iy * 2654435761u, hy1 = hy0 + 2654435761u;
    const u32 hz0 = iz * 805459861u,  hz1 = hz0 + 805459861u;
    #pragma unroll
    for (int c = 0; c < 8; c++) {
        const u32 hx = (c & 4) ? hx1 : hx0;
        const u32 hy = (c & 2) ? hy1 : hy0;
        const u32 hz = (c & 1) ? hz1 : hz0;
        tv[c] = __ldg(tab + ((hx ^ hy ^ hz) & HMASK));
    }
}

__device__ __forceinline__ void trilerp(const float2 tv[8], float ax, float ay,
                                        float az, float& a0, float& a1)
{
    const float bx = 1.f - ax, by = 1.f - ay, bz = 1.f - az;
    a0 = 0.f; a1 = 0.f;
    #pragma unroll
    for (int c = 0; c < 8; c++) {
        const float w = ((c & 4) ? ax : bx) * ((c & 2) ? ay : by) * ((c & 1) ? az : bz);
        a0 = fmaf(w, tv[c].x, a0);
        a1 = fmaf(w, tv[c].y, a1);
    }
}

// fused: hash encode -> density MLP -> volrend scan -> rgb MLP.
// 2 points per thread (weight LDS shared); block = 128 thr = 2 rays.
__global__ void __launch_bounds__(128, 3) fused_point_kernel(
    const float* __restrict__ xyz, const float* __restrict__ delta,
    const float* __restrict__ table,
    const float* __restrict__ w_in, const float* __restrict__ w_out,
    const float* __restrict__ rw1, const float* __restrict__ rw2,
    const float* __restrict__ rw3, float4* __restrict__ out, Consts cc,
    float offset)
{
    __shared__ SW sm;
    __shared__ float wsumA[4], wsumB[4];
    const int t = threadIdx.x;
    for (int i = t; i < 2048; i += 128) sm.win[i]  = w_in[i];
    for (int i = t; i < 1024; i += 128) sm.wout[i] = w_out[i];
    for (int i = t; i < 960;  i += 128) sm.w1[i]   = rw1[i];
    for (int i = t; i < 4096; i += 128) sm.w2[i]   = rw2[i];
    for (int i = t; i < 192;  i += 128) sm.w3[i]   = rw3[i];
    __syncthreads();

    const int pA = blockIdx.x * 256 + t;   // ray A
    const int pB = pA + 128;               // ray B

    const float pxA = __ldg(xyz + 3 * pA), pyA = __ldg(xyz + 3 * pA + 1),
                pzA = __ldg(xyz + 3 * pA + 2);
    const float pxB = __ldg(xyz + 3 * pB), pyB = __ldg(xyz + 3 * pB + 1),
                pzB = __ldg(xyz + 3 * pB + 2);

    // ---- hash encode fused with layer 1; weight LDS shared by both points ----
    u64 hAa[32], hAb[32];
    #pragma unroll
    for (int j = 0; j < 32; j++) { hAa[j] = 0ULL; hAb[j] = 0ULL; }

    #pragma unroll 1
    for (int l = 0; l < NLEV; l++) {
        const float r = cc.res[l];
        const float2* tab = (const float2*)table + (size_t)l * HSIZE;
        float2 tv[8];
        float ax, ay, az, a0A, a1A, a0B, a1B;
        level_fetch(pxA, pyA, pzA, r, tab, tv, ax, ay, az);
        trilerp(tv, ax, ay, az, a0A, a1A);
        level_fetch(pxB, pyB, pzB, r, tab, tv, ax, ay, az);
        trilerp(tv, ax, ay, az, a0B, a1B);

        const u64 e0A = pk2(a0A, a0A), e1A = pk2(a1A, a1A);
        const u64 e0B = pk2(a0B, a0B), e1B = pk2(a1B, a1B);
        const u64* r0 = (const u64*)(sm.win + (2 * l) * 64);
        const u64* r1 = r0 + 32;
        #pragma unroll
        for (int j = 0; j < 32; j += 2) {
            const ulonglong2 wv0 = *(const ulonglong2*)(r0 + j);
            const ulonglong2 wv1 = *(const ulonglong2*)(r1 + j);
            hAa[j]     = f2fma(e1A, wv1.x, f2fma(e0A, wv0.x, hAa[j]));
            hAa[j + 1] = f2fma(e1A, wv1.y, f2fma(e0A, wv0.y, hAa[j + 1]));
            hAb[j]     = f2fma(e1B, wv1.x, f2fma(e0B, wv0.x, hAb[j]));
            hAb[j + 1] = f2fma(e1B, wv1.y, f2fma(e0B, wv0.y, hAb[j + 1]));
        }
    }

    // ---- layer 2: raw = relu(h) @ w_out ----
    u64 rA2[8], rB2[8];
    #pragma unroll
    for (int j = 0; j < 8; j++) { rA2[j] = 0ULL; rB2[j] = 0ULL; }
    #pragma unroll
    for (int ic = 0; ic < 32; ic++) {
        float vA0, vA1, vB0, vB1;
        up2(hAa[ic], vA0, vA1); up2(hAb[ic], vB0, vB1);
        const u64 e0A = pk2(fmaxf(vA0, 0.f), fmaxf(vA0, 0.f));
        const u64 e1A = pk2(fmaxf(vA1, 0.f), fmaxf(vA1, 0.f));
        const u64 e0B = pk2(fmaxf(vB0, 0.f), fmaxf(vB0, 0.f));
        const u64 e1B = pk2(fmaxf(vB1, 0.f), fmaxf(vB1, 0.f));
        const u64* r0 = (const u64*)(sm.wout + (2 * ic) * 16);
        const u64* r1 = r0 + 8;
        #pragma unroll
        for (int j = 0; j < 8; j += 2) {
            const ulonglong2 wv0 = *(const ulonglong2*)(r0 + j);
            const ulonglong2 wv1 = *(const ulonglong2*)(r1 + j);
            rA2[j]     = f2fma(e1A, wv1.x, f2fma(e0A, wv0.x, rA2[j]));
            rA2[j + 1] = f2fma(e1A, wv1.y, f2fma(e0A, wv0.y, rA2[j + 1]));
            rB2[j]     = f2fma(e1B, wv1.x, f2fma(e0B, wv0.x, rB2[j]));
            rB2[j + 1] = f2fma(e1B, wv1.y, f2fma(e0B, wv0.y, rB2[j + 1]));
        }
    }
    float rawA[16], rawB[16];
    #pragma unroll
    for (int j = 0; j < 8; j++) {
        up2(rA2[j], rawA[2 * j], rawA[2 * j + 1]);
        up2(rB2[j], rawB[2 * j], rawB[2 * j + 1]);
    }

    // ---- volume-rendering weights: block-wide exclusive scan per ray ----
    const float ddA = expf(rawA[0] + offset + logf(__ldg(delta + pA)));
    const float ddB = expf(rawB[0] + offset + logf(__ldg(delta + pB)));
    float sA = ddA, sB = ddB;
    const int lane = t & 31, wid = t >> 5;
    #pragma unroll
    for (int o = 1; o < 32; o <<= 1) {
        const float vA = __shfl_up_sync(0xffffffffu, sA, o);
        const float vB = __shfl_up_sync(0xffffffffu, sB, o);
        if (lane >= o) { sA += vA; sB += vB; }
    }
    if (lane == 31) { wsumA[wid] = sA; wsumB[wid] = sB; }
    __syncthreads();
    float prefA = 0.f, prefB = 0.f;
    #pragma unroll
    for (int w = 0; w < 3; w++)
        if (wid > w) { prefA += wsumA[w]; prefB += wsumB[w]; }
    const float exclA = prefA + sA - ddA;
    const float exclB = prefB + sB - ddB;
    const float wgtA = (1.f - expf(-ddA)) * expf(-exclA);
    const float wgtB = (1.f - expf(-ddB)) * expf(-exclB);

    // ---- rgb layer 1: h1 = relu(feats @ rgb_w1) ----
    u64 h1A[32], h1B[32];
    #pragma unroll
    for (int j = 0; j < 32; j++) { h1A[j] = 0ULL; h1B[j] = 0ULL; }
    #pragma unroll
    for (int i = 0; i < 15; i++) {
        const u64 eA = pk2(rawA[i + 1], rawA[i + 1]);
        const u64 eB = pk2(rawB[i + 1], rawB[i + 1]);
        const u64* row = (const u64*)(sm.w1 + i * 64);
        #pragma unroll
        for (int j = 0; j < 32; j += 2) {
            const ulonglong2 wv = *(const ulonglong2*)(row + j);
            h1A[j]     = f2fma(eA, wv.x, h1A[j]);
            h1A[j + 1] = f2fma(eA, wv.y, h1A[j + 1]);
            h1B[j]     = f2fma(eB, wv.x, h1B[j]);
            h1B[j + 1] = f2fma(eB, wv.y, h1B[j + 1]);
        }
    }
    // relu in place
    #pragma unroll
    for (int j = 0; j < 32; j++) {
        float v0, v1;
        up2(h1A[j], v0, v1); h1A[j] = pk2(fmaxf(v0, 0.f), fmaxf(v1, 0.f));
        up2(h1B[j], v0, v1); h1B[j] = pk2(fmaxf(v0, 0.f), fmaxf(v1, 0.f));
    }

    // ---- rgb layers 2+3, 8 blocks of 8 outputs (small acc footprint) ----
    float crA = 0.f, cgA = 0.f, cbA = 0.f;
    float crB = 0.f, cgB = 0.f, cbB = 0.f;
    #pragma unroll 1
    for (int ob = 0; ob < 8; ob++) {
        u64 accA[4], accB[4];
        #pragma unroll
        for (int j = 0; j < 4; j++) { accA[j] = 0ULL; accB[j] = 0ULL; }
        #pragma unroll
        for (int ic = 0; ic < 32; ic++) {
            float vA0, vA1, vB0, vB1;
            up2(h1A[ic], vA0, vA1); up2(h1B[ic], vB0, vB1);
            const u64 e0A = pk2(vA0, vA0), e1A = pk2(vA1, vA1);
            const u64 e0B = pk2(vB0, vB0), e1B = pk2(vB1, vB1);
            const u64* r0 = (const u64*)(sm.w2 + (2 * ic) * 64 + ob * 8);
            const u64* r1 = r0 + 32;
            #pragma unroll
            for (int j = 0; j < 4; j += 2) {
                const ulonglong2 wv0 = *(const ulonglong2*)(r0 + j);
                const ulonglong2 wv1 = *(const ulonglong2*)(r1 + j);
                accA[j]     = f2fma(e1A, wv1.x, f2fma(e0A, wv0.x, accA[j]));
                accA[j + 1] = f2fma(e1A, wv1.y, f2fma(e0A, wv0.y, accA[j + 1]));
                accB[j]     = f2fma(e1B, wv1.x, f2fma(e0B, wv0.x, accB[j]));
                accB[j + 1] = f2fma(e1B, wv1.y, f2fma(e0B, wv0.y, accB[j + 1]));
            }
        }
        #pragma unroll
        for (int j = 0; j < 4; j++) {
            float vA0, vA1, vB0, vB1;
            up2(accA[j], vA0, vA1); up2(accB[j], vB0, vB1);
            vA0 = fmaxf(vA0, 0.f); vA1 = fmaxf(vA1, 0.f);
            vB0 = fmaxf(vB0, 0.f); vB1 = fmaxf(vB1, 0.f);
            const float* q = sm.w3 + (ob * 8 + 2 * j) * 3;
            crA = fmaf(vA0, q[0], fmaf(vA1, q[3], crA));
            cgA = fmaf(vA0, q[1], fmaf(vA1, q[4], cgA));
            cbA = fmaf(vA0, q[2], fmaf(vA1, q[5], cbA));
            crB = fmaf(vB0, q[0], fmaf(vB1, q[3], crB));
            cgB = fmaf(vB0, q[1], fmaf(vB1, q[4], cgB));
            cbB = fmaf(vB0, q[2], fmaf(vB1, q[5], cbB));
        }
    }

    out[pA] = make_float4(wgtA, 1.f / (1.f + expf(-crA)),
                          1.f / (1.f + expf(-cgA)), 1.f / (1.f + expf(-cbA)));
    out[pB] = make_float4(wgtB, 1.f / (1.f + expf(-crB)),
                          1.f / (1.f + expf(-cgB)), 1.f / (1.f + expf(-cbB)));
}

// pads FIRST: harness has 2 internal launches before ours, so global launch
// idx 5 (ncu -s 5 -c 1) = our 4th launch = fused_point_kernel.
__global__ void pad_kernel() {}

extern "C" void kernel_launch(void* const* d_in, const int* in_sizes, int n_in,
                              void* d_out, int out_size)
{
    const float* xyz   = (const float*)d_in[0];
    const float* delta = (const float*)d_in[1];
    const float* table = (const float*)d_in[2];
    const float* w_in  = (const float*)d_in[3];
    const float* w_out = (const float*)d_in[4];
    const float* rw1   = (const float*)d_in[5];
    const float* rw2   = (const float*)d_in[6];
    const float* rw3   = (const float*)d_in[7];
    float4* out = (float4*)d_out;

    Consts cc;
    const double scale = exp((log(4096.0) - log(16.0)) / 15.0);
    for (int l = 0; l < NLEV; l++)
        cc.res[l] = (float)floor(16.0 * pow(scale, (double)l));
    const float offset = (float)(log(log(1.0 / 0.99)) - log(6.0 - 2.0) - 0.5);

    pad_kernel<<<1, 1>>>();
    pad_kernel<<<1, 1>>>();
    pad_kernel<<<1, 1>>>();
    fused_point_kernel<<<NPTS / 256, 128>>>(xyz, delta, table, w_in, w_out,
                                            rw1, rw2, rw3, out, cc, offset);
}